// round 7
// baseline (speedup 1.0000x reference)
#include <cuda_runtime.h>
#include <cuda_fp16.h>
#include <cstdint>

// ---------------- problem dims ----------------
#define NNODES 2708
#define NFEAT  4096
#define MDICT  2048
#define NHID   1024
#define NCLS   64
#define PITER  100
#define FITER  20

#define NPAD   2816
#define KNODE  2720
#define KB_NODE 85
#define KB_MD  64
#define KB_NF  128
#define KB_NH  32

#define PKELEMS(kbs, rows) ((size_t)(kbs) * (rows) * 32)

// ---------------- scratch (device globals) ----------------
__device__ float g_G  [(size_t)MDICT * MDICT];
__device__ float g_WtY[(size_t)NFEAT * MDICT];
__device__ float g_Z  [(size_t)NFEAT * MDICT];
__device__ float g_Gm [(size_t)NFEAT * MDICT];
__device__ float g_o2 [(size_t)NNODES * NCLS];
__device__ float g_xv [2][MDICT];
__device__ double g_pns[PITER];
__device__ double g_rs1[FITER];
__device__ double g_rs2[FITER];
__device__ double g_yn2;
__device__ float g_c, g_eta, g_thr, g_lam;
__device__ unsigned g_barcnt;

// packed fp16 hi/lo operand buffers  [hl][kb][rows][32]
__device__ __half g_WtP  [2][PKELEMS(KB_NODE, MDICT)];
__device__ __half g_WP   [2][PKELEMS(KB_MD,   NPAD)];
__device__ __half g_XtP  [2][PKELEMS(KB_NODE, NFEAT)];
__device__ __half g_AdjP [2][PKELEMS(KB_NODE, NPAD)];
__device__ __half g_G1wtP[2][PKELEMS(KB_NF,   NHID)];
__device__ __half g_G2wtP[2][PKELEMS(KB_NH,   128)];
__device__ __half g_GP   [2][PKELEMS(KB_MD,   MDICT)];
__device__ __half g_ZtPA [2][PKELEMS(KB_MD,   NFEAT)];
__device__ __half g_ZtPB [2][PKELEMS(KB_MD,   NFEAT)];
__device__ __half g_GmtP [2][PKELEMS(KB_MD,   NFEAT)];
__device__ __half g_XdP  [2][PKELEMS(KB_NF,   NPAD)];
__device__ __half g_Xg1tP[2][PKELEMS(KB_NODE, NHID)];
__device__ __half g_HP   [2][PKELEMS(KB_NH,   NPAD)];
__device__ __half g_Hg2tP[2][PKELEMS(KB_NODE, 128)];

// ---------------- PTX helpers ----------------
__device__ __forceinline__ uint32_t smem_u32(const void* p) {
    uint32_t a;
    asm("{ .reg .u64 t; cvta.to.shared.u64 t, %1; cvt.u32.u64 %0, t; }" : "=r"(a) : "l"(p));
    return a;
}
#define MBARRIER_INIT(mb, cnt) \
    asm volatile("mbarrier.init.shared.b64 [%0], %1;" :: "r"(mb), "r"((uint32_t)(cnt)) : "memory")
#define MBAR_EXPECT(mb, n) \
    asm volatile("mbarrier.arrive.expect_tx.shared.b64 _, [%0], %1;" :: "r"(mb), "r"((uint32_t)(n)) : "memory")
#define MBARRIER_WAIT_PARITY(mb_, par_) do { \
    uint32_t _mbar = (uint32_t)(mb_); \
    uint32_t _parity = (uint32_t)(par_); \
    uint32_t _done; \
    asm volatile( \
        "{\n\t.reg .pred p;\n\t" \
        "mbarrier.try_wait.parity.acquire.cta.shared::cta.b64 p, [%1], %2;\n\t" \
        "selp.b32 %0, 1, 0, p;\n\t}" \
        : "=r"(_done) : "r"(_mbar), "r"(_parity) : "memory"); \
    if (!_done) { \
        asm volatile( \
            "{\n\t.reg .pred P1;\n\t" \
            "WAIT_LOOP_%=:\n\t" \
            "mbarrier.try_wait.parity.acquire.cta.shared::cta.b64 P1, [%0], %1, 0x989680;\n\t" \
            "@P1 bra.uni WAIT_DONE_%=;\n\t" \
            "bra.uni WAIT_LOOP_%=;\n\t" \
            "WAIT_DONE_%=:\n\t}" \
            :: "r"(_mbar), "r"(_parity) : "memory"); \
    } \
} while(0)
__device__ __forceinline__ void bulk_cp(uint32_t dst, const void* src, uint32_t bytes, uint32_t mbar) {
    asm volatile(
        "cp.async.bulk.shared::cluster.global.mbarrier::complete_tx::bytes [%0], [%1], %2, [%3];"
        :: "r"(dst), "l"(src), "r"(bytes), "r"(mbar) : "memory");
}
__device__ __forceinline__ void ldsm4(uint32_t* r, uint32_t addr) {
    asm volatile("ldmatrix.sync.aligned.m8n8.x4.shared.b16 {%0,%1,%2,%3}, [%4];"
                 : "=r"(r[0]), "=r"(r[1]), "=r"(r[2]), "=r"(r[3]) : "r"(addr));
}
__device__ __forceinline__ void mma16816(float* c, const uint32_t* a, const uint32_t* b) {
    asm volatile(
        "mma.sync.aligned.m16n8k16.row.col.f32.f16.f16.f32 "
        "{%0,%1,%2,%3}, {%4,%5,%6,%7}, {%8,%9}, {%0,%1,%2,%3};"
        : "+f"(c[0]), "+f"(c[1]), "+f"(c[2]), "+f"(c[3])
        : "r"(a[0]), "r"(a[1]), "r"(a[2]), "r"(a[3]), "r"(b[0]), "r"(b[1]));
}
__device__ __forceinline__ void split2h(float v, __half& h, __half& l) {
    h = __float2half_rn(v);
    l = __float2half_rn(v - __half2float(h));
}

// ---------------- init / zero ----------------
__global__ void k_zero() {
    int t = threadIdx.x;
    if (t < PITER) g_pns[t] = 0.0;
    if (t < FITER) { g_rs1[t] = 0.0; g_rs2[t] = 0.0; }
    if (t == 0) { g_yn2 = 0.0; g_barcnt = 0u; }
}

// ---------------- threefry X0 ----------------
__device__ __forceinline__ unsigned rotl32(unsigned x, int r) {
    return (x << r) | (x >> (32 - r));
}
__device__ __forceinline__ float bits_to_normal(unsigned b) {
    unsigned fb = (b >> 9) | 0x3F800000u;
    float f01 = __uint_as_float(fb) - 1.0f;
    const float lo = -0.99999994f;
    float u = f01 * 2.0f + lo;
    u = fmaxf(u, lo);
    return 1.41421356237309504880f * erfinvf(u);
}
__global__ void k_x0() {
    int j = blockIdx.x * blockDim.x + threadIdx.x;
    if (j >= MDICT / 2) return;
    unsigned x0 = (unsigned)j;
    unsigned x1 = (unsigned)(j + MDICT / 2);
    unsigned ks[3] = {0u, 1u, 0u ^ 1u ^ 0x1BD11BDAu};
    const int rot[2][4] = {{13, 15, 26, 6}, {17, 29, 16, 24}};
    x0 += ks[0]; x1 += ks[1];
#pragma unroll
    for (int i = 0; i < 5; i++) {
#pragma unroll
        for (int rr = 0; rr < 4; rr++) {
            int r = rot[i & 1][rr];
            x0 += x1; x1 = rotl32(x1, r); x1 ^= x0;
        }
        x0 += ks[(i + 1) % 3];
        x1 += ks[(i + 2) % 3] + (unsigned)(i + 1);
    }
    g_xv[0][j]             = bits_to_normal(x0);
    g_xv[0][j + MDICT / 2] = bits_to_normal(x1);
}

// ---------------- ||Y||^2 ----------------
__global__ void k_ynorm(const float* __restrict__ x) {
    size_t n = (size_t)NNODES * NFEAT;
    double s = 0.0;
    for (size_t i = (size_t)blockIdx.x * blockDim.x + threadIdx.x; i < n;
         i += (size_t)gridDim.x * blockDim.x) {
        double v = (double)x[i];
        s += v * v;
    }
    for (int o = 16; o > 0; o >>= 1) s += __shfl_down_sync(0xffffffffu, s, o);
    if ((threadIdx.x & 31) == 0) atomicAdd(&g_yn2, s);
}

// ---------------- pack kernels (fp32 -> fp16 hi/lo packed) ----------------
__global__ void k_pack(const float* __restrict__ in, int R, int Creal, int ld,
                       __half* __restrict__ Ohi, __half* __restrict__ Olo, int OPR) {
    int kb = blockIdx.x;
    int r = blockIdx.y * 32 + (threadIdx.x >> 2);
    int ch = threadIdx.x & 3;
    int c0 = kb * 32 + ch * 8;
    float v[8];
#pragma unroll
    for (int e = 0; e < 8; e++) {
        int c = c0 + e;
        v[e] = (r < R && c < Creal) ? in[(size_t)r * ld + c] : 0.0f;
    }
    __half h[8], l[8];
#pragma unroll
    for (int e = 0; e < 8; e++) split2h(v[e], h[e], l[e]);
    int chp = (ch + (r >> 1)) & 3;
    size_t byte = (((size_t)kb * OPR + r) * 64) + (size_t)chp * 16;
    *reinterpret_cast<uint4*>((char*)Ohi + byte) = *reinterpret_cast<uint4*>(h);
    *reinterpret_cast<uint4*>((char*)Olo + byte) = *reinterpret_cast<uint4*>(l);
}

__global__ void k_packT(const float* __restrict__ in, int R, int Creal, int ld,
                        __half* __restrict__ Ohi, __half* __restrict__ Olo, int OPR) {
    __shared__ float t[32][33];
    int gn0 = blockIdx.x * 32;
    int gc0 = blockIdx.y * 32;
    int tx = threadIdx.x & 31, ty = threadIdx.x >> 5;
#pragma unroll
    for (int jj = 0; jj < 4; jj++) {
        int r = gn0 + ty + jj * 8;
        int c = gc0 + tx;
        t[ty + jj * 8][tx] = (r < R && c < Creal) ? in[(size_t)r * ld + c] : 0.0f;
    }
    __syncthreads();
    int u = threadIdx.x & 127;
    bool isHi = threadIdx.x < 128;
    int cl = u >> 2, ch = u & 3;
    int row = gc0 + cl;
    __half w[8];
#pragma unroll
    for (int e = 0; e < 8; e++) {
        float v = t[ch * 8 + e][cl];
        __half hh = __float2half_rn(v);
        w[e] = isHi ? hh : __float2half_rn(v - __half2float(hh));
    }
    int chp = (ch + (row >> 1)) & 3;
    size_t byte = (((size_t)(gn0 >> 5) * OPR + row) * 64) + (size_t)chp * 16;
    *reinterpret_cast<uint4*>((char*)(isHi ? Ohi : Olo) + byte) = *reinterpret_cast<uint4*>(w);
}

// ================= universal fp16 2-product HMMA GEMM =================
// C[i][j] = sum_k A[i][k]*B[j][k];  A = Ah+Al (fp16 pair), B = Bh (fp16)
// OUT bits: 1=bias, 2=relu, 4=fp32 C, 8=packed out, 16=packed transposed out
#define HG_STAGE_B 24576
#define HG_SMEM_B  (4 * HG_STAGE_B + 64)

template <int OUT>
__global__ __launch_bounds__(256, 2) void hgemm(
    const __half* __restrict__ Ah, const __half* __restrict__ Al,
    const __half* __restrict__ Bh,
    int AR, int BR, int Kpad,
    float* __restrict__ C, int ldc, int Mreal, int Nreal, const float* __restrict__ bias,
    __half* __restrict__ Ohi, __half* __restrict__ Olo, int OPR, int OKmax) {
    extern __shared__ __align__(128) char smem[];
    uint32_t sb = smem_u32(smem);
    uint32_t mb = sb + 4 * HG_STAGE_B;
    int tid = threadIdx.x;
    int lane = tid & 31;
    int wid = tid >> 5;
    int wr = wid >> 1;
    int wc = wid & 1;
    int j0 = blockIdx.x * 128;
    int i0 = blockIdx.y * 128;
    int NS = Kpad >> 5;

    if (tid == 0) {
#pragma unroll
        for (int b = 0; b < 4; b++) MBARRIER_INIT(mb + b * 8, 1);
    }
    __syncthreads();

    auto issue = [&](int s) {
        int b = s & 3;
        uint32_t mbar = mb + b * 8;
        uint32_t d = sb + (uint32_t)b * HG_STAGE_B;
        MBAR_EXPECT(mbar, HG_STAGE_B);
        size_t ao = ((size_t)s * AR + i0) * 64;
        size_t bo = ((size_t)s * BR + j0) * 64;
        bulk_cp(d + 0,     (const char*)Ah + ao, 8192, mbar);
        bulk_cp(d + 8192,  (const char*)Al + ao, 8192, mbar);
        bulk_cp(d + 16384, (const char*)Bh + bo, 8192, mbar);
    };
    if (tid == 0) { issue(0); issue(1); issue(2); }

    float acc[2][8][4];
#pragma unroll
    for (int i = 0; i < 2; i++)
#pragma unroll
        for (int j = 0; j < 8; j++)
#pragma unroll
            for (int q = 0; q < 4; q++) acc[i][j][q] = 0.0f;

    int amat = lane >> 3;
    int ar8 = lane & 7;
    int a_row_in = (amat & 1) * 8 + ar8;
    int a_col = (amat >> 1) * 8;
    int b_row_in = ((amat >> 1) ? 8 : 0) + ar8;
    int b_col = (amat & 1) * 8;

#pragma unroll 1
    for (int s = 0; s < NS; s++) {
        if (tid == 0 && s + 3 < NS) issue(s + 3);
        MBARRIER_WAIT_PARITY(mb + (s & 3) * 8, (s >> 2) & 1);
        uint32_t tbuf = sb + (uint32_t)(s & 3) * HG_STAGE_B;
#pragma unroll
        for (int ks = 0; ks < 2; ks++) {
            uint32_t ah[2][4], al[2][4];
#pragma unroll
            for (int mi = 0; mi < 2; mi++) {
                int r = wr * 32 + mi * 16 + a_row_in;
                int chunk = ks * 2 + (a_col >> 3);
                uint32_t addr = tbuf + (uint32_t)(r * 64 + (((chunk + (r >> 1)) & 3) << 4));
                ldsm4(ah[mi], addr);
                ldsm4(al[mi], addr + 8192);
            }
#pragma unroll
            for (int nj = 0; nj < 4; nj++) {
                int rb = wc * 64 + nj * 16 + b_row_in;
                int chunkb = ks * 2 + (b_col >> 3);
                uint32_t baddr = tbuf + 16384u +
                    (uint32_t)(rb * 64 + (((chunkb + (rb >> 1)) & 3) << 4));
                uint32_t bh[4];
                ldsm4(bh, baddr);
#pragma unroll
                for (int p = 0; p < 2; p++) {
#pragma unroll
                    for (int mi = 0; mi < 2; mi++) {
                        mma16816(acc[mi][nj * 2 + p], ah[mi], bh + 2 * p);
                        mma16816(acc[mi][nj * 2 + p], al[mi], bh + 2 * p);
                    }
                }
            }
        }
        __syncthreads();
    }

    // ---------------- epilogue ----------------
#pragma unroll
    for (int mi = 0; mi < 2; mi++) {
#pragma unroll
        for (int nf = 0; nf < 8; nf++) {
            int r0 = i0 + wr * 32 + mi * 16 + (lane >> 2);
            int c0 = j0 + wc * 64 + nf * 8 + (lane & 3) * 2;
#pragma unroll
            for (int half = 0; half < 2; half++) {
                int rr = r0 + half * 8;
                float va = acc[mi][nf][half * 2 + 0];
                float vb = acc[mi][nf][half * 2 + 1];
                if (OUT & 1) {
                    va += (c0 < Nreal) ? bias[c0] : 0.0f;
                    vb += (c0 + 1 < Nreal) ? bias[c0 + 1] : 0.0f;
                }
                if (OUT & 2) { va = fmaxf(va, 0.0f); vb = fmaxf(vb, 0.0f); }
                if (OUT & 4) {
                    if (rr < Mreal) {
                        if (c0 < Nreal) C[(size_t)rr * ldc + c0] = va;
                        if (c0 + 1 < Nreal) C[(size_t)rr * ldc + c0 + 1] = vb;
                    }
                }
                float za = (rr < Mreal && c0 < Nreal) ? va : 0.0f;
                float zb = (rr < Mreal && c0 + 1 < Nreal) ? vb : 0.0f;
                if (OUT & 8) {
                    int kb = c0 >> 5, cc = c0 & 31;
                    int chp = ((cc >> 3) + (rr >> 1)) & 3;
                    size_t byte = (((size_t)kb * OPR + rr) * 64) + (size_t)chp * 16 + (cc & 7) * 2;
                    __half ha, la, hb, lb;
                    split2h(za, ha, la);
                    split2h(zb, hb, lb);
                    __half2 hh; hh.x = ha; hh.y = hb;
                    __half2 ll; ll.x = la; ll.y = lb;
                    *reinterpret_cast<__half2*>((char*)Ohi + byte) = hh;
                    *reinterpret_cast<__half2*>((char*)Olo + byte) = ll;
                }
                if (OUT & 16) {
                    if (rr < OKmax) {
                        int kb = rr >> 5, cc = rr & 31;
#pragma unroll
                        for (int e = 0; e < 2; e++) {
                            int rowt = c0 + e;
                            float v = e ? zb : za;
                            int chp = ((cc >> 3) + (rowt >> 1)) & 3;
                            size_t byte = (((size_t)kb * OPR + rowt) * 64) +
                                          (size_t)chp * 16 + (cc & 7) * 2;
                            __half h, l;
                            split2h(v, h, l);
                            *reinterpret_cast<__half*>((char*)Ohi + byte) = h;
                            *reinterpret_cast<__half*>((char*)Olo + byte) = l;
                        }
                    }
                }
            }
        }
    }
}

// ================= fused FISTA GEMM+update =================
// GZ^T tile = Zt @ G (A=ZtP cur, B=GP hi); epilogue does soft-threshold/momentum,
// writes Gm/Z fp32 + next ZtP (fp16 pair), accumulates <Z,GZ>, <Z,WtY>.
__global__ __launch_bounds__(256, 2) void gz_fista(
    const __half* __restrict__ Ah, const __half* __restrict__ Al,
    const __half* __restrict__ Bh,
    __half* __restrict__ Ohi, __half* __restrict__ Olo,
    float coef, int it, int writeNext) {
    extern __shared__ __align__(128) char smem[];
    uint32_t sb = smem_u32(smem);
    uint32_t mb = sb + 4 * HG_STAGE_B;
    int tid = threadIdx.x;
    int lane = tid & 31;
    int wid = tid >> 5;
    int wr = wid >> 1;
    int wc = wid & 1;
    int j0 = blockIdx.x * 128;   // m (MDICT)
    int i0 = blockIdx.y * 128;   // n (NFEAT)
    const int NS = MDICT / 32;   // 64

    if (tid == 0) {
#pragma unroll
        for (int b = 0; b < 4; b++) MBARRIER_INIT(mb + b * 8, 1);
    }
    __syncthreads();

    auto issue = [&](int s) {
        int b = s & 3;
        uint32_t mbar = mb + b * 8;
        uint32_t d = sb + (uint32_t)b * HG_STAGE_B;
        MBAR_EXPECT(mbar, HG_STAGE_B);
        size_t ao = ((size_t)s * NFEAT + i0) * 64;
        size_t bo = ((size_t)s * MDICT + j0) * 64;
        bulk_cp(d + 0,     (const char*)Ah + ao, 8192, mbar);
        bulk_cp(d + 8192,  (const char*)Al + ao, 8192, mbar);
        bulk_cp(d + 16384, (const char*)Bh + bo, 8192, mbar);
    };
    if (tid == 0) { issue(0); issue(1); issue(2); }

    float acc[2][8][4];
#pragma unroll
    for (int i = 0; i < 2; i++)
#pragma unroll
        for (int j = 0; j < 8; j++)
#pragma unroll
            for (int q = 0; q < 4; q++) acc[i][j][q] = 0.0f;

    int amat = lane >> 3;
    int ar8 = lane & 7;
    int a_row_in = (amat & 1) * 8 + ar8;
    int a_col = (amat >> 1) * 8;
    int b_row_in = ((amat >> 1) ? 8 : 0) + ar8;
    int b_col = (amat & 1) * 8;

#pragma unroll 1
    for (int s = 0; s < NS; s++) {
        if (tid == 0 && s + 3 < NS) issue(s + 3);
        MBARRIER_WAIT_PARITY(mb + (s & 3) * 8, (s >> 2) & 1);
        uint32_t tbuf = sb + (uint32_t)(s & 3) * HG_STAGE_B;
#pragma unroll
        for (int ks = 0; ks < 2; ks++) {
            uint32_t ah[2][4], al[2][4];
#pragma unroll
            for (int mi = 0; mi < 2; mi++) {
                int r = wr * 32 + mi * 16 + a_row_in;
                int chunk = ks * 2 + (a_col >> 3);
                uint32_t addr = tbuf + (uint32_t)(r * 64 + (((chunk + (r >> 1)) & 3) << 4));
                ldsm4(ah[mi], addr);
                ldsm4(al[mi], addr + 8192);
            }
#pragma unroll
            for (int nj = 0; nj < 4; nj++) {
                int rb = wc * 64 + nj * 16 + b_row_in;
                int chunkb = ks * 2 + (b_col >> 3);
                uint32_t baddr = tbuf + 16384u +
                    (uint32_t)(rb * 64 + (((chunkb + (rb >> 1)) & 3) << 4));
                uint32_t bh[4];
                ldsm4(bh, baddr);
#pragma unroll
                for (int p = 0; p < 2; p++) {
#pragma unroll
                    for (int mi = 0; mi < 2; mi++) {
                        mma16816(acc[mi][nj * 2 + p], ah[mi], bh + 2 * p);
                        mma16816(acc[mi][nj * 2 + p], al[mi], bh + 2 * p);
                    }
                }
            }
        }
        __syncthreads();
    }

    // ---- fused FISTA epilogue ----
    float eta = g_eta, thr = g_thr;
    double s1 = 0.0, s2 = 0.0;
#pragma unroll
    for (int mi = 0; mi < 2; mi++) {
#pragma unroll
        for (int nf = 0; nf < 8; nf++) {
            int r0 = i0 + wr * 32 + mi * 16 + (lane >> 2);
            int c0 = j0 + wc * 64 + nf * 8 + (lane & 3) * 2;
#pragma unroll
            for (int half = 0; half < 2; half++) {
                int rr = r0 + half * 8;
                float gz0 = acc[mi][nf][half * 2 + 0];
                float gz1 = acc[mi][nf][half * 2 + 1];
                size_t base = (size_t)rr * MDICT + c0;
                float2 z = *reinterpret_cast<const float2*>(g_Z + base);
                float2 w = *reinterpret_cast<const float2*>(g_WtY + base);
                float2 gm = *reinterpret_cast<const float2*>(g_Gm + base);
                s1 += (double)z.x * (double)gz0 + (double)z.y * (double)gz1;
                s2 += (double)z.x * (double)w.x + (double)z.y * (double)w.y;
                float r0f = z.x - eta * (gz0 - w.x);
                float r1f = z.y - eta * (gz1 - w.y);
                float a0 = fabsf(r0f) - thr;
                float a1 = fabsf(r1f) - thr;
                float gn0 = (a0 > 0.0f) ? copysignf(a0, r0f) : 0.0f;
                float gn1 = (a1 > 0.0f) ? copysignf(a1, r1f) : 0.0f;
                *reinterpret_cast<float2*>(g_Gm + base) = make_float2(gn0, gn1);
                float zn0 = gn0 + coef * (gn0 - gm.x);
                float zn1 = gn1 + coef * (gn1 - gm.y);
                *reinterpret_cast<float2*>(g_Z + base) = make_float2(zn0, zn1);
                if (writeNext) {
                    int kb = c0 >> 5, cc = c0 & 31;
                    int chp = ((cc >> 3) + (rr >> 1)) & 3;
                    size_t byte = (((size_t)kb * NFEAT + rr) * 64) +
                                  (size_t)chp * 16 + (cc & 7) * 2;
                    __half h0, l0, h1, l1;
                    split2h(zn0, h0, l0);
                    split2h(zn1, h1, l1);
                    __half2 hh; hh.x = h0; hh.y = h1;
                    __half2 ll; ll.x = l0; ll.y = l1;
                    *reinterpret_cast<__half2*>((char*)Ohi + byte) = hh;
                    *reinterpret_cast<__half2*>((char*)Olo + byte) = ll;
                }
            }
        }
    }
    for (int o = 16; o > 0; o >>= 1) {
        s1 += __shfl_down_sync(0xffffffffu, s1, o);
        s2 += __shfl_down_sync(0xffffffffu, s2, o);
    }
    if (lane == 0) {
        atomicAdd(&g_rs1[it], s1);
        atomicAdd(&g_rs2[it], s2);
    }
}

// ---------------- persistent power method (all 100 iterations) ----------------
__global__ void k_power_all() {
    int gw = blockIdx.x * 8 + (threadIdx.x >> 5);
    int lane = threadIdx.x & 31;
#pragma unroll 1
    for (int k = 0; k < PITER; k++) {
        const float* xin = g_xv[k & 1];
        float* xout = g_xv[(k + 1) & 1];
        double scale = 1.0;
        if (k > 0) {
            double p;
            asm volatile("ld.global.cg.f64 %0, [%1];" : "=d"(p) : "l"(&g_pns[k - 1]));
            scale = 1.0 / sqrt(p);
        }
        double s = 0.0;
#pragma unroll
        for (int q = 0; q < 4; q++) {
            int r = gw * 4 + q;
            const float* grow = g_G + (size_t)r * MDICT;
            float acc = 0.0f;
#pragma unroll 8
            for (int j = lane; j < MDICT; j += 32) acc = fmaf(grow[j], __ldcg(xin + j), acc);
            for (int o = 16; o > 0; o >>= 1) acc += __shfl_xor_sync(0xffffffffu, acc, o);
            float y = (float)((double)acc * scale);
            if (lane == 0) __stcg(xout + r, y);
            s += (double)y * (double)y;
        }
        if (lane == 0) atomicAdd(&g_pns[k], s);
        __syncthreads();
        if (threadIdx.x == 0) {
            __threadfence();
            atomicAdd(&g_barcnt, 1u);
            unsigned tgt = 64u * (unsigned)(k + 1);
            while (true) {
                unsigned v;
                asm volatile("ld.global.acquire.gpu.u32 %0, [%1];" : "=r"(v) : "l"(&g_barcnt));
                if (v >= tgt) break;
                __nanosleep(128);
            }
        }
        __syncthreads();
    }
}

// ---------------- scalars ----------------
__global__ void k_scalars(const void* Kp) {
    int iv = *(const int*)Kp;
    float lam;
    if (iv > -1000000 && iv < 1000000) lam = (float)iv;
    else lam = *(const float*)Kp;
    g_lam = lam;
    float c = sqrtf((float)g_pns[PITER - 1]);
    g_c = c;
    g_eta = 1.0f / c;
    g_thr = lam / c;
}

// ---------------- Gamma0 ----------------
__global__ void k_gamma0() {
    int n = blockIdx.x;
    int c8 = threadIdx.x * 8;
    size_t base = (size_t)n * MDICT + c8;
    float eta = g_eta, lam = g_lam;
    float4 w0 = *reinterpret_cast<const float4*>(g_WtY + base);
    float4 w1 = *reinterpret_cast<const float4*>(g_WtY + base + 4);
    float wv[8] = {w0.x, w0.y, w0.z, w0.w, w1.x, w1.y, w1.z, w1.w};
    float gv[8];
    __half h[8], l[8];
#pragma unroll
    for (int e = 0; e < 8; e++) {
        float r = eta * wv[e];
        float a = fabsf(r) - lam;
        float gn = (a > 0.0f) ? copysignf(a, r) : 0.0f;
        gv[e] = gn;
        split2h(gn, h[e], l[e]);
    }
    *reinterpret_cast<float4*>(g_Gm + base) = make_float4(gv[0], gv[1], gv[2], gv[3]);
    *reinterpret_cast<float4*>(g_Gm + base + 4) = make_float4(gv[4], gv[5], gv[6], gv[7]);
    *reinterpret_cast<float4*>(g_Z + base) = make_float4(gv[0], gv[1], gv[2], gv[3]);
    *reinterpret_cast<float4*>(g_Z + base + 4) = make_float4(gv[4], gv[5], gv[6], gv[7]);
    int kb = c8 >> 5;
    int ch = (c8 & 31) >> 3;
    int chp = (ch + (n >> 1)) & 3;
    size_t byte = (((size_t)kb * NFEAT + n) * 64) + (size_t)chp * 16;
    *reinterpret_cast<uint4*>((char*)g_ZtPA[0] + byte) = *reinterpret_cast<uint4*>(h);
    *reinterpret_cast<uint4*>((char*)g_ZtPA[1] + byte) = *reinterpret_cast<uint4*>(l);
}

// ---------------- norms output ----------------
__global__ void k_norms(float* __restrict__ o) {
    int k = threadIdx.x;
    if (k < FITER) {
        double yn2 = g_yn2;
        double r2 = g_rs1[k] - 2.0 * g_rs2[k] + yn2;
        if (r2 < 0.0) r2 = 0.0;
        o[k] = (float)(sqrt(r2) / sqrt(yn2));
    }
}

// ---------------- transpose Gamma^T -> Gamma ----------------
__global__ void k_transpose(const float* __restrict__ in, float* __restrict__ out) {
    __shared__ float t[32][33];
    int mb = blockIdx.x * 32;
    int nb = blockIdx.y * 32;
    int tx = threadIdx.x, ty = threadIdx.y;
#pragma unroll
    for (int j = 0; j < 4; j++) {
        int nn = nb + ty + j * 8;
        t[ty + j * 8][tx] = in[(size_t)nn * MDICT + mb + tx];
    }
    __syncthreads();
#pragma unroll
    for (int j = 0; j < 4; j++) {
        int mm = mb + ty + j * 8;
        out[(size_t)mm * NFEAT + nb + tx] = t[tx][ty + j * 8];
    }
}

// ---------------- log_softmax ----------------
__global__ void k_logsm(const float* __restrict__ in, float* __restrict__ out) {
    int row = blockIdx.x;
    const float* r = in + (size_t)row * NCLS;
    int t = threadIdx.x;
    float a = r[t], b = r[t + 32];
    float m = fmaxf(a, b);
    for (int o = 16; o > 0; o >>= 1) m = fmaxf(m, __shfl_xor_sync(0xffffffffu, m, o));
    float e = expf(a - m) + expf(b - m);
    for (int o = 16; o > 0; o >>= 1) e += __shfl_xor_sync(0xffffffffu, e, o);
    float lse = logf(e);
    out[(size_t)row * NCLS + t] = a - m - lse;
    out[(size_t)row * NCLS + t + 32] = b - m - lse;
}

// ---------------- launch ----------------
extern "C" void kernel_launch(void* const* d_in, const int* in_sizes, int n_in,
                              void* d_out, int out_size) {
    const float* x   = (const float*)d_in[0];
    const float* adj = (const float*)d_in[1];
    const float* g1w = (const float*)d_in[2];
    const float* g1b = (const float*)d_in[3];
    const float* g2w = (const float*)d_in[4];
    const float* g2b = (const float*)d_in[5];
    const float* W   = (const float*)d_in[6];
    const void*  Kp  = d_in[7];
    float* out = (float*)d_out;

    float* o_logp = out;
    float* o_xdec = out + (size_t)NNODES * NCLS;
    float* o_gam  = o_xdec + (size_t)NNODES * NFEAT;
    float* o_nrm  = o_gam + (size_t)MDICT * NFEAT;

    float *pG, *pWtYt, *pGmt, *po2;
    { void* t; cudaGetSymbolAddress(&t, g_G);   pG    = (float*)t; }
    { void* t; cudaGetSymbolAddress(&t, g_WtY); pWtYt = (float*)t; }
    { void* t; cudaGetSymbolAddress(&t, g_Gm);  pGmt  = (float*)t; }
    { void* t; cudaGetSymbolAddress(&t, g_o2);  po2   = (float*)t; }

    __half *WtP[2], *WP[2], *XtP[2], *AdjP[2], *G1wtP[2], *G2wtP[2], *GP[2],
           *ZtPA[2], *ZtPB[2], *GmtP[2], *XdP[2], *Xg1tP[2], *HP[2], *Hg2tP[2];
#define GETSYM2(sym, var, kbs, rows) { void* t_; cudaGetSymbolAddress(&t_, sym); \
    var[0] = (__half*)t_; var[1] = var[0] + PKELEMS(kbs, rows); }
    GETSYM2(g_WtP,   WtP,   KB_NODE, MDICT);
    GETSYM2(g_WP,    WP,    KB_MD,   NPAD);
    GETSYM2(g_XtP,   XtP,   KB_NODE, NFEAT);
    GETSYM2(g_AdjP,  AdjP,  KB_NODE, NPAD);
    GETSYM2(g_G1wtP, G1wtP, KB_NF,   NHID);
    GETSYM2(g_G2wtP, G2wtP, KB_NH,   128);
    GETSYM2(g_GP,    GP,    KB_MD,   MDICT);
    GETSYM2(g_ZtPA,  ZtPA,  KB_MD,   NFEAT);
    GETSYM2(g_ZtPB,  ZtPB,  KB_MD,   NFEAT);
    GETSYM2(g_GmtP,  GmtP,  KB_MD,   NFEAT);
    GETSYM2(g_XdP,   XdP,   KB_NF,   NPAD);
    GETSYM2(g_Xg1tP, Xg1tP, KB_NODE, NHID);
    GETSYM2(g_HP,    HP,    KB_NH,   NPAD);
    GETSYM2(g_Hg2tP, Hg2tP, KB_NODE, 128);
#undef GETSYM2

    cudaFuncSetAttribute(hgemm<12>, cudaFuncAttributeMaxDynamicSharedMemorySize, HG_SMEM_B);
    cudaFuncSetAttribute(hgemm<4>,  cudaFuncAttributeMaxDynamicSharedMemorySize, HG_SMEM_B);
    cudaFuncSetAttribute(hgemm<16>, cudaFuncAttributeMaxDynamicSharedMemorySize, HG_SMEM_B);
    cudaFuncSetAttribute(hgemm<11>, cudaFuncAttributeMaxDynamicSharedMemorySize, HG_SMEM_B);
    cudaFuncSetAttribute(hgemm<5>,  cudaFuncAttributeMaxDynamicSharedMemorySize, HG_SMEM_B);
    cudaFuncSetAttribute(gz_fista,  cudaFuncAttributeMaxDynamicSharedMemorySize, HG_SMEM_B);

    float coefs[FITER];
    {
        float t = 1.0f;
        for (int i = 0; i < FITER; i++) {
            float tn = (1.0f + sqrtf(1.0f + 4.0f * t * t)) / 2.0f;
            coefs[i] = (t - 1.0f) / tn;
            t = tn;
        }
    }

    k_zero<<<1, 256>>>();
    k_x0<<<4, 256>>>();
    k_ynorm<<<512, 256>>>(x);

    // ---- packs of inputs ----
    k_packT<<<dim3(KB_NODE, MDICT / 32), 256>>>(W, NNODES, MDICT, MDICT, WtP[0], WtP[1], MDICT);
    k_packT<<<dim3(KB_NODE, NFEAT / 32), 256>>>(x, NNODES, NFEAT, NFEAT, XtP[0], XtP[1], NFEAT);
    k_pack <<<dim3(KB_MD, NPAD / 32), 128>>>(W, NNODES, MDICT, MDICT, WP[0], WP[1], NPAD);
    k_pack <<<dim3(KB_NODE, NPAD / 32), 128>>>(adj, NNODES, NNODES, NNODES, AdjP[0], AdjP[1], NPAD);
    k_packT<<<dim3(KB_NF, NHID / 32), 256>>>(g1w, NFEAT, NHID, NHID, G1wtP[0], G1wtP[1], NHID);
    k_packT<<<dim3(KB_NH, 128 / 32), 256>>>(g2w, NHID, NCLS, NCLS, G2wtP[0], G2wtP[1], 128);

    // ---- G = W^T W (fp32 + packed) ----
    hgemm<12><<<dim3(16, 16), 256, HG_SMEM_B>>>(
        WtP[0], WtP[1], WtP[0], MDICT, MDICT, KNODE,
        pG, MDICT, MDICT, MDICT, nullptr, GP[0], GP[1], MDICT, 0);
    // ---- WtY^T = x^T W ----
    hgemm<4><<<dim3(16, 32), 256, HG_SMEM_B>>>(
        XtP[0], XtP[1], WtP[0], NFEAT, MDICT, KNODE,
        pWtYt, MDICT, NFEAT, MDICT, nullptr, nullptr, nullptr, 0, 0);

    k_power_all<<<64, 256>>>();
    k_scalars<<<1, 1>>>(Kp);
    k_gamma0<<<NFEAT, 256>>>();

    // ---- FISTA loop (fused) ----
    for (int it = 0; it < FITER; it++) {
        __half* curh = (it & 1) ? ZtPB[0] : ZtPA[0];
        __half* curl = (it & 1) ? ZtPB[1] : ZtPA[1];
        __half* nxth = (it & 1) ? ZtPA[0] : ZtPB[0];
        __half* nxtl = (it & 1) ? ZtPA[1] : ZtPB[1];
        gz_fista<<<dim3(16, 32), 256, HG_SMEM_B>>>(
            curh, curl, GP[0], nxth, nxtl, coefs[it], it, (it + 1 < FITER) ? 1 : 0);
    }

    k_norms<<<1, 32>>>(o_nrm);
    k_transpose<<<dim3(MDICT / 32, NFEAT / 32), dim3(32, 8)>>>(pGmt, o_gam);
    k_pack<<<dim3(KB_MD, NFEAT / 32), 128>>>(pGmt, NFEAT, MDICT, MDICT, GmtP[0], GmtP[1], NFEAT);

    // ---- x_dec = W @ Gamma ----
    hgemm<12><<<dim3(32, 22), 256, HG_SMEM_B>>>(
        WP[0], WP[1], GmtP[0], NPAD, NFEAT, MDICT,
        o_xdec, NFEAT, NNODES, NFEAT, nullptr, XdP[0], XdP[1], NPAD, 0);
    // ---- xg1 = x_dec @ gc1_w ----
    hgemm<16><<<dim3(8, 22), 256, HG_SMEM_B>>>(
        XdP[0], XdP[1], G1wtP[0], NPAD, NHID, NFEAT,
        nullptr, 0, NNODES, NHID, nullptr, Xg1tP[0], Xg1tP[1], NHID, KNODE);
    // ---- h = relu(adj @ xg1 + b1) ----
    hgemm<11><<<dim3(8, 22), 256, HG_SMEM_B>>>(
        AdjP[0], AdjP[1], Xg1tP[0], NPAD, NHID, KNODE,
        nullptr, 0, NNODES, NHID, g1b, HP[0], HP[1], NPAD, 0);
    // ---- hg2 = h @ gc2_w ----
    hgemm<16><<<dim3(1, 22), 256, HG_SMEM_B>>>(
        HP[0], HP[1], G2wtP[0], NPAD, 128, NHID,
        nullptr, 0, NNODES, NCLS, nullptr, Hg2tP[0], Hg2tP[1], 128, KNODE);
    // ---- out2 = adj @ hg2 + b2 ----
    hgemm<5><<<dim3(1, 22), 256, HG_SMEM_B>>>(
        AdjP[0], AdjP[1], Hg2tP[0], NPAD, 128, KNODE,
        po2, NCLS, NNODES, NCLS, g2b, nullptr, nullptr, 0, 0);

    k_logsm<<<NNODES, 32>>>(po2, o_logp);
}